// round 2
// baseline (speedup 1.0000x reference)
#include <cuda_runtime.h>
#include <math.h>

#define CDIV(a,b) (((a)+(b)-1)/(b))

static const int B  = 32;
static const int C  = 256;
static const int NZ = 225;   // 15*15
static const int NX = 961;   // 31*31
static const int KDIM = 2304; // C*9

// ---------------- scratch (device globals; no cudaMalloc allowed) ----------
__device__ float g_attnA[32 * 256 * 256];          // 8.4 MB  (attn of z)
__device__ float g_attnB[32 * 256 * 256];          // 8.4 MB  (attn of x)
__device__ float g_featZ[32 * 256 * 225];          // 7.4 MB
__device__ float g_featX[32 * 256 * 961];          // 31.5 MB
__device__ float g_off  [32 * 18  * 961];          // 2.2 MB
__device__ float g_col  [2304 * 32 * 961];         // 283.4 MB im2col (reused)

// ---------------------------------------------------------------------------
// gram: E[b] = F[b] * F[b]^T    (F: [C][N] row-major)   64x64 tile, BK=16
// ---------------------------------------------------------------------------
__global__ __launch_bounds__(256) void gram_kernel(const float* __restrict__ F,
                                                   float* __restrict__ E, int N) {
    __shared__ float As[16][68];
    __shared__ float Bs[16][68];
    int b = blockIdx.z;
    const float* Fb = F + (size_t)b * C * N;
    int c0 = blockIdx.x * 64, d0 = blockIdx.y * 64;
    int tid = threadIdx.y * 16 + threadIdx.x;
    int kk = tid & 15;
    int r4 = (tid >> 4) * 4;
    float acc[4][4] = {};
    for (int k0 = 0; k0 < N; k0 += 16) {
        bool kin = (k0 + kk) < N;
#pragma unroll
        for (int q = 0; q < 4; q++) {
            int row = r4 + q;
            As[kk][row] = kin ? Fb[(size_t)(c0 + row) * N + k0 + kk] : 0.f;
            Bs[kk][row] = kin ? Fb[(size_t)(d0 + row) * N + k0 + kk] : 0.f;
        }
        __syncthreads();
#pragma unroll
        for (int k = 0; k < 16; k++) {
            float4 a4 = *(const float4*)&As[k][threadIdx.y * 4];
            float4 b4 = *(const float4*)&Bs[k][threadIdx.x * 4];
            float av[4] = {a4.x, a4.y, a4.z, a4.w};
            float bv[4] = {b4.x, b4.y, b4.z, b4.w};
#pragma unroll
            for (int i = 0; i < 4; i++)
#pragma unroll
                for (int j = 0; j < 4; j++) acc[i][j] += av[i] * bv[j];
        }
        __syncthreads();
    }
    float* Eb = E + (size_t)b * C * C;
#pragma unroll
    for (int i = 0; i < 4; i++)
#pragma unroll
        for (int j = 0; j < 4; j++)
            Eb[(size_t)(c0 + threadIdx.y * 4 + i) * C + d0 + threadIdx.x * 4 + j] = acc[i][j];
}

// ---------------------------------------------------------------------------
// softmax of (rowmax - e) over last dim  ==  exp(rowmin - e)/sum
// one block per row (b*C rows), 256 threads
// ---------------------------------------------------------------------------
__global__ __launch_bounds__(256) void attn_softmax_kernel(float* __restrict__ E) {
    int row = blockIdx.x;
    float* e = E + (size_t)row * 256;
    int t = threadIdx.x;
    float v = e[t];
    __shared__ float red[256];
    red[t] = v;
    __syncthreads();
    for (int s = 128; s > 0; s >>= 1) {
        if (t < s) red[t] = fminf(red[t], red[t + s]);
        __syncthreads();
    }
    float emin = red[0];
    __syncthreads();
    float p = expf(emin - v);
    red[t] = p;
    __syncthreads();
    for (int s = 128; s > 0; s >>= 1) {
        if (t < s) red[t] += red[t + s];
        __syncthreads();
    }
    e[t] = p / red[0];
}

// ---------------------------------------------------------------------------
// cam_use: O[b] = gamma * A[b] @ F[b] + F[b]   (A: CxC, F: CxN)  64x64 tile
// ---------------------------------------------------------------------------
__global__ __launch_bounds__(256) void camuse_kernel(const float* __restrict__ A,
                                                     const float* __restrict__ F,
                                                     float* __restrict__ O, int N,
                                                     const float* __restrict__ gamma) {
    __shared__ float As[16][68];
    __shared__ float Bs[16][68];
    int b = blockIdx.z;
    const float* Ab = A + (size_t)b * C * C;
    const float* Fb = F + (size_t)b * C * N;
    int c0 = blockIdx.x * 64, n0 = blockIdx.y * 64;
    int tid = threadIdx.y * 16 + threadIdx.x;
    int kkA = tid & 15;
    int r4 = (tid >> 4) * 4;
    float acc[4][4] = {};
    for (int k0 = 0; k0 < C; k0 += 16) {
#pragma unroll
        for (int q = 0; q < 4; q++) {
            int row = r4 + q;
            As[kkA][row] = Ab[(size_t)(c0 + row) * C + k0 + kkA];
        }
#pragma unroll
        for (int q = 0; q < 4; q++) {
            int idx = tid + q * 256;
            int kk = idx >> 6, n = idx & 63;
            Bs[kk][n] = (n0 + n < N) ? Fb[(size_t)(k0 + kk) * N + n0 + n] : 0.f;
        }
        __syncthreads();
#pragma unroll
        for (int k = 0; k < 16; k++) {
            float4 a4 = *(const float4*)&As[k][threadIdx.y * 4];
            float4 b4 = *(const float4*)&Bs[k][threadIdx.x * 4];
            float av[4] = {a4.x, a4.y, a4.z, a4.w};
            float bv[4] = {b4.x, b4.y, b4.z, b4.w};
#pragma unroll
            for (int i = 0; i < 4; i++)
#pragma unroll
                for (int j = 0; j < 4; j++) acc[i][j] += av[i] * bv[j];
        }
        __syncthreads();
    }
    float g = gamma[0];
#pragma unroll
    for (int i = 0; i < 4; i++) {
        int c = c0 + threadIdx.y * 4 + i;
#pragma unroll
        for (int j = 0; j < 4; j++) {
            int n = n0 + threadIdx.x * 4 + j;
            if (n < N)
                O[((size_t)b * C + c) * N + n] = g * acc[i][j] + Fb[(size_t)c * N + n];
        }
    }
}

// ---------------------------------------------------------------------------
// offset conv: 3x3, C -> 18, pad 1.  grid (ntile, 18, B), 128 threads
// ---------------------------------------------------------------------------
__global__ __launch_bounds__(128) void offconv_kernel(const float* __restrict__ feat,
                                                      const float* __restrict__ woff,
                                                      const float* __restrict__ boff,
                                                      float* __restrict__ off,
                                                      int H, int W) {
    __shared__ float sw[2304];
    int ch = blockIdx.y, b = blockIdx.z;
    const float* wp = woff + (size_t)ch * 2304;
    for (int i = threadIdx.x; i < 2304; i += 128) sw[i] = wp[i];
    __syncthreads();
    int N = H * W;
    int n = blockIdx.x * 128 + threadIdx.x;
    if (n >= N) return;
    int h = n / W, w = n % W;
    const float* fb = feat + (size_t)b * C * N;
    float acc = boff[ch];
    for (int c = 0; c < C; c++) {
        const float* fc = fb + (size_t)c * N;
        const float* swc = sw + c * 9;
#pragma unroll
        for (int ky = 0; ky < 3; ky++) {
            int y = h + ky - 1;
            if ((unsigned)y >= (unsigned)H) continue;
            const float* fr = fc + y * W;
#pragma unroll
            for (int kx = 0; kx < 3; kx++) {
                int x = w + kx - 1;
                if ((unsigned)x < (unsigned)W) acc += swc[ky * 3 + kx] * fr[x];
            }
        }
    }
    off[((size_t)b * 18 + ch) * N + n] = acc;
}

// ---------------------------------------------------------------------------
// bilinear deform sampling -> im2col   col[(c*9+k)][b*N + n]
// grid (ntile, 9, B), 128 threads
// ---------------------------------------------------------------------------
__global__ __launch_bounds__(128) void sample_kernel(const float* __restrict__ feat,
                                                     const float* __restrict__ off,
                                                     float* __restrict__ col,
                                                     int H, int W, int Ntot) {
    int N = H * W;
    int b = blockIdx.z, k = blockIdx.y;
    int n = blockIdx.x * 128 + threadIdx.x;
    if (n >= N) return;
    int h = n / W, w = n % W;
    int ky = k / 3, kx = k % 3;
    float oy = off[((size_t)b * 18 + 2 * k) * N + n];
    float ox = off[((size_t)b * 18 + 2 * k + 1) * N + n];
    float py = (float)(h + ky - 1) + oy;
    float px = (float)(w + kx - 1) + ox;
    float y0f = floorf(py), x0f = floorf(px);
    float ly = py - y0f, lx = px - x0f;
    float Hm1 = (float)(H - 1), Wm1 = (float)(W - 1);

    float vy0 = (y0f >= 0.f && y0f <= Hm1) ? (1.f - ly) : 0.f;
    float vy1 = (y0f + 1.f >= 0.f && y0f + 1.f <= Hm1) ? ly : 0.f;
    float vx0 = (x0f >= 0.f && x0f <= Wm1) ? (1.f - lx) : 0.f;
    float vx1 = (x0f + 1.f >= 0.f && x0f + 1.f <= Wm1) ? lx : 0.f;
    int y0 = (int)fminf(fmaxf(y0f, 0.f), Hm1);
    int y1 = (int)fminf(fmaxf(y0f + 1.f, 0.f), Hm1);
    int x0 = (int)fminf(fmaxf(x0f, 0.f), Wm1);
    int x1 = (int)fminf(fmaxf(x0f + 1.f, 0.f), Wm1);

    int i00 = y0 * W + x0, i01 = y0 * W + x1, i10 = y1 * W + x0, i11 = y1 * W + x1;
    float w00 = vy0 * vx0, w01 = vy0 * vx1, w10 = vy1 * vx0, w11 = vy1 * vx1;

    const float* fb = feat + (size_t)b * C * N;
    float* cp = col + (size_t)k * Ntot + (size_t)b * N + n;
    const size_t cstride = (size_t)9 * Ntot;
    for (int c = 0; c < C; c++) {
        const float* fc = fb + (size_t)c * N;
        float v = w00 * fc[i00] + w01 * fc[i01] + w10 * fc[i10] + w11 * fc[i11];
        cp[(size_t)c * cstride] = v;
    }
}

// ---------------------------------------------------------------------------
// main deform GEMM:  out = W[256 x 2304] @ col[2304 x Ntot]
// 128x128 tile, BK=16, 8x8 per thread, 256 threads.
// epilogue scatters column j = b*Nsp + n into out[b][m][n]
// ---------------------------------------------------------------------------
__global__ __launch_bounds__(256) void dconv_gemm_kernel(const float* __restrict__ Wm,
                                                         const float* __restrict__ Bc,
                                                         float* __restrict__ out,
                                                         int Nsp, int Ntot) {
    __shared__ float As[16][132];
    __shared__ float Bs[16][132];
    int m0 = blockIdx.y * 128;
    int n0 = blockIdx.x * 128;
    int tid = threadIdx.y * 16 + threadIdx.x;
    int arow = tid >> 1, akq = (tid & 1) * 8;
    int bkk = tid >> 4, bn8 = (tid & 15) * 8;
    float acc[8][8] = {};
    for (int k0 = 0; k0 < KDIM; k0 += 16) {
        const float* ap = Wm + (size_t)(m0 + arow) * KDIM + k0 + akq;
        float4 a0 = *(const float4*)ap;
        float4 a1 = *(const float4*)(ap + 4);
        As[akq + 0][arow] = a0.x; As[akq + 1][arow] = a0.y;
        As[akq + 2][arow] = a0.z; As[akq + 3][arow] = a0.w;
        As[akq + 4][arow] = a1.x; As[akq + 5][arow] = a1.y;
        As[akq + 6][arow] = a1.z; As[akq + 7][arow] = a1.w;

        const float* bp = Bc + (size_t)(k0 + bkk) * Ntot + n0 + bn8;
        float4 b0 = make_float4(0.f, 0.f, 0.f, 0.f);
        float4 b1 = make_float4(0.f, 0.f, 0.f, 0.f);
        if (n0 + bn8 < Ntot)     b0 = *(const float4*)bp;        // Ntot % 8 == 0
        if (n0 + bn8 + 4 < Ntot) b1 = *(const float4*)(bp + 4);
        *(float4*)&Bs[bkk][bn8]     = b0;
        *(float4*)&Bs[bkk][bn8 + 4] = b1;
        __syncthreads();
#pragma unroll
        for (int k = 0; k < 16; k++) {
            float4 a4 = *(const float4*)&As[k][threadIdx.y * 8];
            float4 a5 = *(const float4*)&As[k][threadIdx.y * 8 + 4];
            float4 b4 = *(const float4*)&Bs[k][threadIdx.x * 8];
            float4 b5 = *(const float4*)&Bs[k][threadIdx.x * 8 + 4];
            float av[8] = {a4.x, a4.y, a4.z, a4.w, a5.x, a5.y, a5.z, a5.w};
            float bv[8] = {b4.x, b4.y, b4.z, b4.w, b5.x, b5.y, b5.z, b5.w};
#pragma unroll
            for (int i = 0; i < 8; i++)
#pragma unroll
                for (int j = 0; j < 8; j++) acc[i][j] += av[i] * bv[j];
        }
        __syncthreads();
    }
#pragma unroll
    for (int i = 0; i < 8; i++) {
        int m = m0 + threadIdx.y * 8 + i;
#pragma unroll
        for (int j = 0; j < 8; j++) {
            int jj = n0 + threadIdx.x * 8 + j;
            if (jj < Ntot) {
                int bb = jj / Nsp;
                int n = jj - bb * Nsp;
                out[((size_t)bb * C + m) * Nsp + n] = acc[i][j];
            }
        }
    }
}

// ---------------------------------------------------------------------------
extern "C" void kernel_launch(void* const* d_in, const int* in_sizes, int n_in,
                              void* d_out, int out_size) {
    const float *Z[3], *X[3], *OW[3], *OB[3], *DW[3], *G[3];
    int nz = 0, nx = 0, nw = 0, nb = 0, nd = 0, ng = 0;
    for (int i = 0; i < n_in; i++) {
        switch (in_sizes[i]) {
            case 1843200: Z[nz++]  = (const float*)d_in[i]; break;  // z: 32*256*225
            case 7872512: X[nx++]  = (const float*)d_in[i]; break;  // x: 32*256*961
            case 41472:   OW[nw++] = (const float*)d_in[i]; break;  // offw: 18*256*9
            case 18:      OB[nb++] = (const float*)d_in[i]; break;  // offb
            case 589824:  DW[nd++] = (const float*)d_in[i]; break;  // dw: 256*256*9
            case 1:       G[ng++]  = (const float*)d_in[i]; break;  // gamma
            default: break;
        }
    }

    float *attnA, *attnB, *featZ, *featX, *offb, *colb;
    cudaGetSymbolAddress((void**)&attnA, g_attnA);
    cudaGetSymbolAddress((void**)&attnB, g_attnB);
    cudaGetSymbolAddress((void**)&featZ, g_featZ);
    cudaGetSymbolAddress((void**)&featX, g_featX);
    cudaGetSymbolAddress((void**)&offb,  g_off);
    cudaGetSymbolAddress((void**)&colb,  g_col);

    float* outZ = (float*)d_out;
    float* outX = outZ + (size_t)3 * B * C * NZ;   // z stack first, then x stack

    dim3 tb(16, 16);
    for (int i = 0; i < 3; i++) {
        // --- channel attention (cross: z uses x's attn and vice versa) ---
        gram_kernel<<<dim3(4, 4, B), tb>>>(Z[i], attnA, NZ);
        attn_softmax_kernel<<<B * C, 256>>>(attnA);
        gram_kernel<<<dim3(4, 4, B), tb>>>(X[i], attnB, NX);
        attn_softmax_kernel<<<B * C, 256>>>(attnB);
        camuse_kernel<<<dim3(4, CDIV(NZ, 64), B), tb>>>(attnB, Z[i], featZ, NZ, G[i]);
        camuse_kernel<<<dim3(4, CDIV(NX, 64), B), tb>>>(attnA, X[i], featX, NX, G[i]);

        // --- z branch: offsets -> deform im2col -> GEMM ---
        offconv_kernel<<<dim3(CDIV(NZ, 128), 18, B), 128>>>(featZ, OW[i], OB[i], offb, 15, 15);
        sample_kernel<<<dim3(CDIV(NZ, 128), 9, B), 128>>>(featZ, offb, colb, 15, 15, B * NZ);
        dconv_gemm_kernel<<<dim3(CDIV(B * NZ, 128), 2), tb>>>(DW[i], colb,
                                                              outZ + (size_t)i * B * C * NZ,
                                                              NZ, B * NZ);
        // --- x branch ---
        offconv_kernel<<<dim3(CDIV(NX, 128), 18, B), 128>>>(featX, OW[i], OB[i], offb, 31, 31);
        sample_kernel<<<dim3(CDIV(NX, 128), 9, B), 128>>>(featX, offb, colb, 31, 31, B * NX);
        dconv_gemm_kernel<<<dim3(CDIV(B * NX, 128), 2), tb>>>(DW[i], colb,
                                                              outX + (size_t)i * B * C * NX,
                                                              NX, B * NX);
    }
    (void)out_size;
}

// round 4
// speedup vs baseline: 1.5461x; 1.5461x over previous
#include <cuda_runtime.h>
#include <math.h>
#include <stdint.h>

#define CDIV(a,b) (((a)+(b)-1)/(b))

static const int B  = 32;
static const int C  = 256;
static const int NZ = 225;   // 15*15
static const int NX = 961;   // 31*31
static const int KDIM = 2304; // C*9

// ---------------- scratch (device globals; no cudaMalloc allowed) ----------
__device__ float g_attnA[32 * 256 * 256];
__device__ float g_attnB[32 * 256 * 256];
__device__ float g_featZ[32 * 256 * 225];
__device__ float g_featX[32 * 256 * 961];
__device__ float g_off  [32 * 18  * 961];
__device__ float g_col  [2304 * 32 * 1024];   // padded im2col (302 MB)
__device__ float g_wr   [256 * 2304];         // tf32-rounded weights

// ======================= PTX helpers =======================================
__device__ __forceinline__ uint32_t smem_u32(const void* p) {
    uint32_t a;
    asm("{ .reg .u64 t; cvta.to.shared.u64 t, %1; cvt.u32.u64 %0, t; }" : "=r"(a) : "l"(p));
    return a;
}
__device__ __forceinline__ void cpa16(uint32_t dst, const void* src) {
    asm volatile("cp.async.cg.shared.global [%0], [%1], 16;" :: "r"(dst), "l"(src));
}
__device__ __forceinline__ float round_tf32(float v) {
    uint32_t r;
    asm("cvt.rna.tf32.f32 %0, %1;" : "=r"(r) : "f"(v));
    return __uint_as_float(r);
}
__device__ __forceinline__ void mma_tf32(float& c0, float& c1, float& c2, float& c3,
                                         uint32_t a0, uint32_t a1, uint32_t a2, uint32_t a3,
                                         uint32_t b0, uint32_t b1) {
    asm volatile(
        "mma.sync.aligned.m16n8k8.row.col.f32.tf32.tf32.f32 "
        "{%0,%1,%2,%3},{%4,%5,%6,%7},{%8,%9},{%0,%1,%2,%3};"
        : "+f"(c0), "+f"(c1), "+f"(c2), "+f"(c3)
        : "r"(a0), "r"(a1), "r"(a2), "r"(a3), "r"(b0), "r"(b1));
}

// ---------------------------------------------------------------------------
// gram: E[b] = F[b] * F[b]^T
// ---------------------------------------------------------------------------
__global__ __launch_bounds__(256) void gram_kernel(const float* __restrict__ F,
                                                   float* __restrict__ E, int N) {
    __shared__ float As[16][68];
    __shared__ float Bs[16][68];
    int b = blockIdx.z;
    const float* Fb = F + (size_t)b * C * N;
    int c0 = blockIdx.x * 64, d0 = blockIdx.y * 64;
    int tid = threadIdx.y * 16 + threadIdx.x;
    int kk = tid & 15;
    int r4 = (tid >> 4) * 4;
    float acc[4][4] = {};
    for (int k0 = 0; k0 < N; k0 += 16) {
        bool kin = (k0 + kk) < N;
#pragma unroll
        for (int q = 0; q < 4; q++) {
            int row = r4 + q;
            As[kk][row] = kin ? Fb[(size_t)(c0 + row) * N + k0 + kk] : 0.f;
            Bs[kk][row] = kin ? Fb[(size_t)(d0 + row) * N + k0 + kk] : 0.f;
        }
        __syncthreads();
#pragma unroll
        for (int k = 0; k < 16; k++) {
            float4 a4 = *(const float4*)&As[k][threadIdx.y * 4];
            float4 b4 = *(const float4*)&Bs[k][threadIdx.x * 4];
            float av[4] = {a4.x, a4.y, a4.z, a4.w};
            float bv[4] = {b4.x, b4.y, b4.z, b4.w};
#pragma unroll
            for (int i = 0; i < 4; i++)
#pragma unroll
                for (int j = 0; j < 4; j++) acc[i][j] += av[i] * bv[j];
        }
        __syncthreads();
    }
    float* Eb = E + (size_t)b * C * C;
#pragma unroll
    for (int i = 0; i < 4; i++)
#pragma unroll
        for (int j = 0; j < 4; j++)
            Eb[(size_t)(c0 + threadIdx.y * 4 + i) * C + d0 + threadIdx.x * 4 + j] = acc[i][j];
}

// ---------------------------------------------------------------------------
// softmax of (rowmax - e) == exp(rowmin - e)/sum
// ---------------------------------------------------------------------------
__global__ __launch_bounds__(256) void attn_softmax_kernel(float* __restrict__ E) {
    int row = blockIdx.x;
    float* e = E + (size_t)row * 256;
    int t = threadIdx.x;
    float v = e[t];
    __shared__ float red[256];
    red[t] = v;
    __syncthreads();
    for (int s = 128; s > 0; s >>= 1) {
        if (t < s) red[t] = fminf(red[t], red[t + s]);
        __syncthreads();
    }
    float emin = red[0];
    __syncthreads();
    float p = expf(emin - v);
    red[t] = p;
    __syncthreads();
    for (int s = 128; s > 0; s >>= 1) {
        if (t < s) red[t] += red[t + s];
        __syncthreads();
    }
    e[t] = p / red[0];
}

// ---------------------------------------------------------------------------
// cam_use: O[b] = gamma * A[b] @ F[b] + F[b]
// ---------------------------------------------------------------------------
__global__ __launch_bounds__(256) void camuse_kernel(const float* __restrict__ A,
                                                     const float* __restrict__ F,
                                                     float* __restrict__ O, int N,
                                                     const float* __restrict__ gamma) {
    __shared__ float As[16][68];
    __shared__ float Bs[16][68];
    int b = blockIdx.z;
    const float* Ab = A + (size_t)b * C * C;
    const float* Fb = F + (size_t)b * C * N;
    int c0 = blockIdx.x * 64, n0 = blockIdx.y * 64;
    int tid = threadIdx.y * 16 + threadIdx.x;
    int kkA = tid & 15;
    int r4 = (tid >> 4) * 4;
    float acc[4][4] = {};
    for (int k0 = 0; k0 < C; k0 += 16) {
#pragma unroll
        for (int q = 0; q < 4; q++) {
            int row = r4 + q;
            As[kkA][row] = Ab[(size_t)(c0 + row) * C + k0 + kkA];
        }
#pragma unroll
        for (int q = 0; q < 4; q++) {
            int idx = tid + q * 256;
            int kk = idx >> 6, n = idx & 63;
            Bs[kk][n] = (n0 + n < N) ? Fb[(size_t)(k0 + kk) * N + n0 + n] : 0.f;
        }
        __syncthreads();
#pragma unroll
        for (int k = 0; k < 16; k++) {
            float4 a4 = *(const float4*)&As[k][threadIdx.y * 4];
            float4 b4 = *(const float4*)&Bs[k][threadIdx.x * 4];
            float av[4] = {a4.x, a4.y, a4.z, a4.w};
            float bv[4] = {b4.x, b4.y, b4.z, b4.w};
#pragma unroll
            for (int i = 0; i < 4; i++)
#pragma unroll
                for (int j = 0; j < 4; j++) acc[i][j] += av[i] * bv[j];
        }
        __syncthreads();
    }
    float g = gamma[0];
#pragma unroll
    for (int i = 0; i < 4; i++) {
        int c = c0 + threadIdx.y * 4 + i;
#pragma unroll
        for (int j = 0; j < 4; j++) {
            int n = n0 + threadIdx.x * 4 + j;
            if (n < N)
                O[((size_t)b * C + c) * N + n] = g * acc[i][j] + Fb[(size_t)c * N + n];
        }
    }
}

// ---------------------------------------------------------------------------
// offset conv: 3x3, C -> 18, pad 1
// ---------------------------------------------------------------------------
__global__ __launch_bounds__(128) void offconv_kernel(const float* __restrict__ feat,
                                                      const float* __restrict__ woff,
                                                      const float* __restrict__ boff,
                                                      float* __restrict__ off,
                                                      int H, int W) {
    __shared__ float sw[2304];
    int ch = blockIdx.y, b = blockIdx.z;
    const float* wp = woff + (size_t)ch * 2304;
    for (int i = threadIdx.x; i < 2304; i += 128) sw[i] = wp[i];
    __syncthreads();
    int N = H * W;
    int n = blockIdx.x * 128 + threadIdx.x;
    if (n >= N) return;
    int h = n / W, w = n % W;
    const float* fb = feat + (size_t)b * C * N;
    float acc = boff[ch];
    for (int c = 0; c < C; c++) {
        const float* fc = fb + (size_t)c * N;
        const float* swc = sw + c * 9;
#pragma unroll
        for (int ky = 0; ky < 3; ky++) {
            int y = h + ky - 1;
            if ((unsigned)y >= (unsigned)H) continue;
            const float* fr = fc + y * W;
#pragma unroll
            for (int kx = 0; kx < 3; kx++) {
                int x = w + kx - 1;
                if ((unsigned)x < (unsigned)W) acc += swc[ky * 3 + kx] * fr[x];
            }
        }
    }
    off[((size_t)b * 18 + ch) * N + n] = acc;
}

// ---------------------------------------------------------------------------
// bilinear deform sampling -> padded im2col, tf32-rounded values
// col[(c*9+k)][b*Npad + n]
// ---------------------------------------------------------------------------
__global__ __launch_bounds__(128) void sample_kernel(const float* __restrict__ feat,
                                                     const float* __restrict__ off,
                                                     float* __restrict__ col,
                                                     int H, int W, int Npad, int NtotPad) {
    int N = H * W;
    int b = blockIdx.z, k = blockIdx.y;
    int n = blockIdx.x * 128 + threadIdx.x;
    if (n >= N) return;
    int h = n / W, w = n % W;
    int ky = k / 3, kx = k % 3;
    float oy = off[((size_t)b * 18 + 2 * k) * N + n];
    float ox = off[((size_t)b * 18 + 2 * k + 1) * N + n];
    float py = (float)(h + ky - 1) + oy;
    float px = (float)(w + kx - 1) + ox;
    float y0f = floorf(py), x0f = floorf(px);
    float ly = py - y0f, lx = px - x0f;
    float Hm1 = (float)(H - 1), Wm1 = (float)(W - 1);

    float vy0 = (y0f >= 0.f && y0f <= Hm1) ? (1.f - ly) : 0.f;
    float vy1 = (y0f + 1.f >= 0.f && y0f + 1.f <= Hm1) ? ly : 0.f;
    float vx0 = (x0f >= 0.f && x0f <= Wm1) ? (1.f - lx) : 0.f;
    float vx1 = (x0f + 1.f >= 0.f && x0f + 1.f <= Wm1) ? lx : 0.f;
    int y0 = (int)fminf(fmaxf(y0f, 0.f), Hm1);
    int y1 = (int)fminf(fmaxf(y0f + 1.f, 0.f), Hm1);
    int x0 = (int)fminf(fmaxf(x0f, 0.f), Wm1);
    int x1 = (int)fminf(fmaxf(x0f + 1.f, 0.f), Wm1);

    int i00 = y0 * W + x0, i01 = y0 * W + x1, i10 = y1 * W + x0, i11 = y1 * W + x1;
    float w00 = vy0 * vx0, w01 = vy0 * vx1, w10 = vy1 * vx0, w11 = vy1 * vx1;

    const float* fb = feat + (size_t)b * C * N;
    float* cp = col + (size_t)k * NtotPad + (size_t)b * Npad + n;
    const size_t cstride = (size_t)9 * NtotPad;
    for (int c = 0; c < C; c++) {
        const float* fc = fb + (size_t)c * N;
        float v = w00 * fc[i00] + w01 * fc[i01] + w10 * fc[i10] + w11 * fc[i11];
        cp[(size_t)c * cstride] = round_tf32(v);
    }
}

// ---------------------------------------------------------------------------
// round W to tf32 once per scale
// ---------------------------------------------------------------------------
__global__ __launch_bounds__(256) void wround_kernel(const float* __restrict__ in,
                                                     float* __restrict__ out, int n) {
    int i = blockIdx.x * 256 + threadIdx.x;
    if (i < n) out[i] = round_tf32(in[i]);
}

// ---------------------------------------------------------------------------
// tf32 mma.sync GEMM:  out = W[256 x 2304] @ col[2304 x NtotPad]
// CTA 128x128, BK=16, 8 warps (2M x 4N), warp tile 64x32, double-buffer cp.async
//   A smem: [128][20] floats (pad for conflict-free frag loads)
//   B smem: [16][136] floats
// ---------------------------------------------------------------------------
#define A_STRIDE 20
#define B_STRIDE 136

__global__ __launch_bounds__(256) void dconv_mma_kernel(const float* __restrict__ Wm,
                                                        const float* __restrict__ Bc,
                                                        float* __restrict__ out,
                                                        int Nsp, int NtotPad, int shift) {
    __shared__ float sA[2][128 * A_STRIDE];
    __shared__ float sB[2][16 * B_STRIDE];

    int tid = threadIdx.x;
    int wid = tid >> 5, lane = tid & 31;
    int g = lane >> 2, t = lane & 3;
    int warpM = wid >> 2;         // 0..1
    int warpN = wid & 3;          // 0..3

    int n0 = blockIdx.x * 128;
    int m0 = blockIdx.y * 128;
    int bb = n0 >> shift;
    int nl0 = n0 & ((1 << shift) - 1);

    uint32_t sAu = smem_u32(&sA[0][0]);
    uint32_t sBu = smem_u32(&sB[0][0]);

    // ---- stage loader: A 512 chunks of 16B, B 512 chunks of 16B ----
    auto load_stage = [&](int stg, int k0) {
        uint32_t aBase = sAu + stg * (128 * A_STRIDE * 4);
        uint32_t bBase = sBu + stg * (16 * B_STRIDE * 4);
#pragma unroll
        for (int i = 0; i < 2; i++) {
            int q = tid + i * 256;
            int row = q >> 2, c16 = q & 3;      // A: 128 rows x 4 chunks
            cpa16(aBase + (row * A_STRIDE + c16 * 4) * 4,
                  Wm + (size_t)(m0 + row) * KDIM + k0 + c16 * 4);
        }
#pragma unroll
        for (int i = 0; i < 2; i++) {
            int q = tid + i * 256;
            int row = q >> 5, c = q & 31;       // B: 16 rows x 32 chunks
            cpa16(bBase + (row * B_STRIDE + c * 4) * 4,
                  Bc + (size_t)(k0 + row) * NtotPad + n0 + c * 4);
        }
    };

    float acc[4][4][4];
#pragma unroll
    for (int i = 0; i < 4; i++)
#pragma unroll
        for (int j = 0; j < 4; j++)
#pragma unroll
            for (int r = 0; r < 4; r++) acc[i][j][r] = 0.f;

    const int ITERS = KDIM / 16;   // 144
    load_stage(0, 0);
    asm volatile("cp.async.commit_group;" ::: "memory");

    for (int it = 0; it < ITERS; ++it) {
        int cur = it & 1;
        if (it + 1 < ITERS) load_stage(cur ^ 1, (it + 1) * 16);
        asm volatile("cp.async.commit_group;" ::: "memory");
        asm volatile("cp.async.wait_group 1;" ::: "memory");
        __syncthreads();

        const float* A0 = &sA[cur][0];
        const float* B0 = &sB[cur][0];
#pragma unroll
        for (int ks = 0; ks < 2; ks++) {
            int kb = ks * 8;
            uint32_t af[4][4];
#pragma unroll
            for (int mt = 0; mt < 4; mt++) {
                int m = warpM * 64 + mt * 16 + g;
                af[mt][0] = __float_as_uint(A0[m * A_STRIDE + kb + t]);
                af[mt][1] = __float_as_uint(A0[(m + 8) * A_STRIDE + kb + t]);
                af[mt][2] = __float_as_uint(A0[m * A_STRIDE + kb + t + 4]);
                af[mt][3] = __float_as_uint(A0[(m + 8) * A_STRIDE + kb + t + 4]);
            }
            uint32_t bf[4][2];
#pragma unroll
            for (int nt = 0; nt < 4; nt++) {
                int n = warpN * 32 + nt * 8 + g;
                bf[nt][0] = __float_as_uint(B0[(kb + t) * B_STRIDE + n]);
                bf[nt][1] = __float_as_uint(B0[(kb + t + 4) * B_STRIDE + n]);
            }
#pragma unroll
            for (int mt = 0; mt < 4; mt++)
#pragma unroll
                for (int nt = 0; nt < 4; nt++)
                    mma_tf32(acc[mt][nt][0], acc[mt][nt][1], acc[mt][nt][2], acc[mt][nt][3],
                             af[mt][0], af[mt][1], af[mt][2], af[mt][3],
                             bf[nt][0], bf[nt][1]);
        }
        __syncthreads();
    }

    // ---- epilogue: c0=C[g][2t], c1=C[g][2t+1], c2=C[g+8][2t], c3=C[g+8][2t+1] ----
#pragma unroll
    for (int mt = 0; mt < 4; mt++) {
        int m = m0 + warpM * 64 + mt * 16 + g;
        float* r0 = out + ((size_t)bb * C + m) * Nsp;
        float* r1 = out + ((size_t)bb * C + m + 8) * Nsp;
#pragma unroll
        for (int nt = 0; nt < 4; nt++) {
            int n = nl0 + warpN * 32 + nt * 8 + t * 2;
            if (n < Nsp) {
                r0[n] = acc[mt][nt][0];
                r1[n] = acc[mt][nt][2];
                if (n + 1 < Nsp) {
                    r0[n + 1] = acc[mt][nt][1];
                    r1[n + 1] = acc[mt][nt][3];
                }
            }
        }
    }
}

// ---------------------------------------------------------------------------
extern "C" void kernel_launch(void* const* d_in, const int* in_sizes, int n_in,
                              void* d_out, int out_size) {
    const float *Z[3], *X[3], *OW[3], *OB[3], *DW[3], *G[3];
    int nz = 0, nx = 0, nw = 0, nb = 0, nd = 0, ng = 0;
    for (int i = 0; i < n_in; i++) {
        switch (in_sizes[i]) {
            case 1843200: Z[nz++]  = (const float*)d_in[i]; break;
            case 7872512: X[nx++]  = (const float*)d_in[i]; break;
            case 41472:   OW[nw++] = (const float*)d_in[i]; break;
            case 18:      OB[nb++] = (const float*)d_in[i]; break;
            case 589824:  DW[nd++] = (const float*)d_in[i]; break;
            case 1:       G[ng++]  = (const float*)d_in[i]; break;
            default: break;
        }
    }

    float *attnA, *attnB, *featZ, *featX, *offb, *colb, *wrb;
    cudaGetSymbolAddress((void**)&attnA, g_attnA);
    cudaGetSymbolAddress((void**)&attnB, g_attnB);
    cudaGetSymbolAddress((void**)&featZ, g_featZ);
    cudaGetSymbolAddress((void**)&featX, g_featX);
    cudaGetSymbolAddress((void**)&offb,  g_off);
    cudaGetSymbolAddress((void**)&colb,  g_col);
    cudaGetSymbolAddress((void**)&wrb,   g_wr);

    float* outZ = (float*)d_out;
    float* outX = outZ + (size_t)3 * B * C * NZ;

    const int NPAD_Z = 256,  SH_Z = 8;
    const int NPAD_X = 1024, SH_X = 10;
    const int NTOT_Z = B * NPAD_Z;   // 8192
    const int NTOT_X = B * NPAD_X;   // 32768

    dim3 tb(16, 16);
    for (int i = 0; i < 3; i++) {
        gram_kernel<<<dim3(4, 4, B), tb>>>(Z[i], attnA, NZ);
        attn_softmax_kernel<<<B * C, 256>>>(attnA);
        gram_kernel<<<dim3(4, 4, B), tb>>>(X[i], attnB, NX);
        attn_softmax_kernel<<<B * C, 256>>>(attnB);
        camuse_kernel<<<dim3(4, CDIV(NZ, 64), B), tb>>>(attnB, Z[i], featZ, NZ, G[i]);
        camuse_kernel<<<dim3(4, CDIV(NX, 64), B), tb>>>(attnA, X[i], featX, NX, G[i]);

        wround_kernel<<<CDIV(256 * KDIM, 256), 256>>>(DW[i], wrb, 256 * KDIM);

        // z branch
        offconv_kernel<<<dim3(CDIV(NZ, 128), 18, B), 128>>>(featZ, OW[i], OB[i], offb, 15, 15);
        sample_kernel<<<dim3(CDIV(NZ, 128), 9, B), 128>>>(featZ, offb, colb, 15, 15, NPAD_Z, NTOT_Z);
        dconv_mma_kernel<<<dim3(NTOT_Z / 128, 2), 256>>>(wrb, colb,
                                                         outZ + (size_t)i * B * C * NZ,
                                                         NZ, NTOT_Z, SH_Z);
        // x branch
        offconv_kernel<<<dim3(CDIV(NX, 128), 18, B), 128>>>(featX, OW[i], OB[i], offb, 31, 31);
        sample_kernel<<<dim3(CDIV(NX, 128), 9, B), 128>>>(featX, offb, colb, 31, 31, NPAD_X, NTOT_X);
        dconv_mma_kernel<<<dim3(NTOT_X / 128, 2), 256>>>(wrb, colb,
                                                         outX + (size_t)i * B * C * NX,
                                                         NX, NTOT_X, SH_X);
    }
    (void)out_size;
}